// round 5
// baseline (speedup 1.0000x reference)
#include <cuda_runtime.h>
#include <cuda_bf16.h>
#include <cstdint>

#define SEQ   2048
#define EMB   1024
#define BATCH 4
#define MTOT  (BATCH * SEQ)   // 8192

// 3-segment split widths
#define K1 (3 * EMB)   // 3072
#define K2 (3 * SEQ)   // 6144

// ---------------- scratch (device globals; allocation-free) ----------------
__device__ __nv_bfloat16 g_xb [(long long)MTOT * K1];
__device__ __nv_bfloat16 g_Wqb[(long long)EMB  * K1];
__device__ __nv_bfloat16 g_Wkb[(long long)EMB  * K1];
__device__ __nv_bfloat16 g_Wvb[(long long)EMB  * K1];
__device__ __nv_bfloat16 g_Wob[(long long)EMB  * K1];
__device__ __nv_bfloat16 g_Qb [(long long)MTOT * K1];
__device__ __nv_bfloat16 g_Kb [(long long)MTOT * K1];
__device__ __nv_bfloat16 g_VTb[(long long)BATCH * EMB * K2];
__device__ float         g_S  [(long long)BATCH * SEQ * SEQ];
__device__ __nv_bfloat16 g_Pb [(long long)BATCH * SEQ * K2];
__device__ __nv_bfloat16 g_Ob [(long long)MTOT * K1];

// ---------------- helpers ----------------
__device__ __forceinline__ uint32_t smem_to_u32(const void* p) {
    uint32_t a;
    asm("{ .reg .u64 t; cvta.to.shared.u64 t, %1; cvt.u32.u64 %0, t; }" : "=r"(a) : "l"(p));
    return a;
}

#define CP_ASYNC16(dst, src) \
    asm volatile("cp.async.cg.shared.global [%0], [%1], 16;" :: "r"(dst), "l"(src))
#define CP_COMMIT() asm volatile("cp.async.commit_group;" ::: "memory")

__device__ __forceinline__ void ldmatrix_x4(uint32_t& r0, uint32_t& r1, uint32_t& r2, uint32_t& r3,
                                            uint32_t addr) {
    asm volatile("ldmatrix.sync.aligned.m8n8.x4.shared.b16 {%0,%1,%2,%3}, [%4];"
                 : "=r"(r0), "=r"(r1), "=r"(r2), "=r"(r3) : "r"(addr));
}

__device__ __forceinline__ void mma16816(float* c, uint32_t a0, uint32_t a1, uint32_t a2, uint32_t a3,
                                         uint32_t b0, uint32_t b1) {
    asm volatile("mma.sync.aligned.m16n8k16.row.col.f32.bf16.bf16.f32 "
                 "{%0,%1,%2,%3}, {%4,%5,%6,%7}, {%8,%9}, {%0,%1,%2,%3};"
                 : "+f"(c[0]), "+f"(c[1]), "+f"(c[2]), "+f"(c[3])
                 : "r"(a0), "r"(a1), "r"(a2), "r"(a3), "r"(b0), "r"(b1));
}

// ---------------- conversion: fp32 -> 3-segment split along K ----------------
// LAYOUT 0 (A): [hi | lo | hi],  LAYOUT 1 (B): [hi | hi | lo]
template <int LAYOUT>
__global__ __launch_bounds__(256)
void cvt_split3(const float* __restrict__ in, __nv_bfloat16* __restrict__ out,
                int C, long long total)
{
    long long idx = (long long)blockIdx.x * blockDim.x + threadIdx.x;
    if (idx >= total) return;
    long long r = idx / C;
    int c = (int)(idx - r * C);
    float x = in[idx];
    __nv_bfloat16 h = __float2bfloat16(x);
    __nv_bfloat16 l = __float2bfloat16(x - __bfloat162float(h));
    long long ro = r * (3LL * C);
    if (LAYOUT == 0) {
        out[ro + c] = h;
        out[ro + C + c] = l;
        out[ro + 2LL * C + c] = h;
    } else {
        out[ro + c] = h;
        out[ro + C + c] = h;
        out[ro + 2LL * C + c] = l;
    }
}

// ---------------- HMMA GEMM: C = alpha * A * B^T (+bias) ----------------
// Block 128(M) x 256(N), BK=64. 8 warps as 2M x 4N, warp tile 64x64.
// 4-stage cp.async pipeline, single __syncthreads per chunk.
// EPI: 0 = fp32 out
//      1 = split-A bf16 out (row stride 3*Nlog; hi, lo, hi)
//      2 = split-B bf16 out (row stride 3*Nlog; hi, hi, lo)
//      3 = split-B transpose out (V^T: [b][n][3*SEQ]; hi, hi, lo)
#define BK      64
#define NSTAGE  4
#define A_BYTES 16384                 // 128 x 64 x 2
#define B_BYTES 32768                 // 256 x 64 x 2
#define STAGE_BYTES (A_BYTES + B_BYTES)   // 48 KB
#define GEMM_SMEM (NSTAGE * STAGE_BYTES)  // 192 KB

template <int EPI, bool HAS_BIAS>
__global__ __launch_bounds__(256, 1)
void mma_gemm(const __nv_bfloat16* __restrict__ A, const __nv_bfloat16* __restrict__ B,
              const float* __restrict__ bias, void* __restrict__ Out,
              int Nlog, int Ktot, float alpha,
              long long sA, long long sB, long long sO)
{
    extern __shared__ __align__(1024) char smem[];
    const uint32_t smem_base = smem_to_u32(smem);
    const int tid = threadIdx.x;
    const int wid = tid >> 5;
    const int lane = tid & 31;
    const int warp_m = wid & 1;      // 0..1 -> 64-row slab
    const int warp_n = wid >> 1;     // 0..3 -> 64-col slab

    A += (long long)blockIdx.z * sA;
    B += (long long)blockIdx.z * sB;

    const int m0 = blockIdx.y * 128;
    const int n0 = blockIdx.x * 256;

    const int nchunks = Ktot / BK;

    auto load_stage = [&](int chunk, int s) {
        uint32_t sa = smem_base + s * STAGE_BYTES;
        uint32_t sb = sa + A_BYTES;
        long long k0 = (long long)chunk * BK;
        #pragma unroll
        for (int t = 0; t < 4; t++) {               // A: 1024 granules
            int idx = tid + t * 256;
            int r = idx >> 3, c = idx & 7;
            uint32_t off = (uint32_t)((r * 8 + (c ^ (r & 7))) * 16);
            CP_ASYNC16(sa + off, (const void*)(A + (long long)(m0 + r) * Ktot + k0 + c * 8));
        }
        #pragma unroll
        for (int t = 0; t < 8; t++) {               // B: 2048 granules
            int idx = tid + t * 256;
            int r = idx >> 3, c = idx & 7;
            uint32_t off = (uint32_t)((r * 8 + (c ^ (r & 7))) * 16);
            CP_ASYNC16(sb + off, (const void*)(B + (long long)(n0 + r) * Ktot + k0 + c * 8));
        }
        CP_COMMIT();
    };

    float acc[4][8][4];
    #pragma unroll
    for (int mi = 0; mi < 4; mi++)
        #pragma unroll
        for (int ni = 0; ni < 8; ni++)
            #pragma unroll
            for (int r = 0; r < 4; r++)
                acc[mi][ni][r] = 0.0f;

    load_stage(0, 0);
    load_stage(1, 1);
    load_stage(2, 2);

    const int a_row = (lane & 15);
    const int a_half = lane >> 4;
    const int b_noff = (lane & 7) + ((lane & 16) ? 8 : 0);
    const int b_kg = (lane & 8) ? 1 : 0;

    for (int i = 0; i < nchunks; i++) {
        if (i + 2 < nchunks) {
            asm volatile("cp.async.wait_group 2;" ::: "memory");
        } else if (i + 1 < nchunks) {
            asm volatile("cp.async.wait_group 1;" ::: "memory");
        } else {
            asm volatile("cp.async.wait_group 0;" ::: "memory");
        }
        __syncthreads();

        if (i + 3 < nchunks) load_stage(i + 3, (i + 3) & (NSTAGE - 1));

        const int s = i & (NSTAGE - 1);
        const uint32_t sa = smem_base + s * STAGE_BYTES;
        const uint32_t sb = sa + A_BYTES;

        #pragma unroll
        for (int kk = 0; kk < 4; kk++) {
            uint32_t af[4][4];
            #pragma unroll
            for (int mi = 0; mi < 4; mi++) {
                int row = warp_m * 64 + mi * 16 + a_row;
                int g = (kk * 2 + a_half) ^ (row & 7);
                ldmatrix_x4(af[mi][0], af[mi][1], af[mi][2], af[mi][3],
                            sa + (uint32_t)((row * 8 + g) * 16));
            }
            uint32_t bf[4][4];
            #pragma unroll
            for (int nt = 0; nt < 4; nt++) {
                int row = warp_n * 64 + nt * 16 + b_noff;
                int g = (kk * 2 + b_kg) ^ (row & 7);
                ldmatrix_x4(bf[nt][0], bf[nt][1], bf[nt][2], bf[nt][3],
                            sb + (uint32_t)((row * 8 + g) * 16));
            }
            #pragma unroll
            for (int mi = 0; mi < 4; mi++)
                #pragma unroll
                for (int ni = 0; ni < 8; ni++) {
                    int nt = ni >> 1;
                    uint32_t b0 = (ni & 1) ? bf[nt][2] : bf[nt][0];
                    uint32_t b1 = (ni & 1) ? bf[nt][3] : bf[nt][1];
                    mma16816(acc[mi][ni], af[mi][0], af[mi][1], af[mi][2], af[mi][3], b0, b1);
                }
        }
    }

    // ---- epilogue ----
    const int rbase = m0 + warp_m * 64 + (lane >> 2);
    const int cbase = n0 + warp_n * 64 + (lane & 3) * 2;

    #pragma unroll
    for (int mi = 0; mi < 4; mi++) {
        #pragma unroll
        for (int ni = 0; ni < 8; ni++) {
            #pragma unroll
            for (int half = 0; half < 2; half++) {
                int gm = rbase + mi * 16 + half * 8;
                int gn = cbase + ni * 8;
                float v0 = acc[mi][ni][half * 2 + 0] * alpha;
                float v1 = acc[mi][ni][half * 2 + 1] * alpha;
                if (HAS_BIAS) { v0 += bias[gn]; v1 += bias[gn + 1]; }
                if (EPI == 0) {
                    float* O = (float*)Out + (long long)blockIdx.z * sO;
                    float2* p = (float2*)&O[(long long)gm * Nlog + gn];
                    *p = make_float2(v0, v1);
                } else if (EPI == 1 || EPI == 2) {
                    __nv_bfloat16* O = (__nv_bfloat16*)Out + (long long)blockIdx.z * sO;
                    long long ro = (long long)gm * (3LL * Nlog);
                    __nv_bfloat16 h0 = __float2bfloat16(v0);
                    __nv_bfloat16 l0 = __float2bfloat16(v0 - __bfloat162float(h0));
                    __nv_bfloat16 h1 = __float2bfloat16(v1);
                    __nv_bfloat16 l1 = __float2bfloat16(v1 - __bfloat162float(h1));
                    if (EPI == 1) {
                        *(__nv_bfloat162*)&O[ro + gn] = __nv_bfloat162(h0, h1);
                        *(__nv_bfloat162*)&O[ro + Nlog + gn] = __nv_bfloat162(l0, l1);
                        *(__nv_bfloat162*)&O[ro + 2LL * Nlog + gn] = __nv_bfloat162(h0, h1);
                    } else {
                        *(__nv_bfloat162*)&O[ro + gn] = __nv_bfloat162(h0, h1);
                        *(__nv_bfloat162*)&O[ro + Nlog + gn] = __nv_bfloat162(h0, h1);
                        *(__nv_bfloat162*)&O[ro + 2LL * Nlog + gn] = __nv_bfloat162(l0, l1);
                    }
                } else {
                    __nv_bfloat16* O = (__nv_bfloat16*)Out;
                    int b = gm >> 11;
                    int sdx = gm & (SEQ - 1);
                    #pragma unroll
                    for (int e = 0; e < 2; e++) {
                        float v = e ? v1 : v0;
                        int n = gn + e;
                        __nv_bfloat16 h = __float2bfloat16(v);
                        __nv_bfloat16 l = __float2bfloat16(v - __bfloat162float(h));
                        long long base = (long long)b * Nlog * (3LL * SEQ)
                                       + (long long)n * (3LL * SEQ) + sdx;
                        O[base] = h;
                        O[base + SEQ] = h;
                        O[base + 2 * SEQ] = l;
                    }
                }
            }
        }
    }
}

// ---------------- softmax (fp32 in) -> split-A bf16 P ----------------
__global__ __launch_bounds__(256)
void softmax_split(const float* __restrict__ S, __nv_bfloat16* __restrict__ P)
{
    long long row = blockIdx.x;
    const float* in = S + row * SEQ;
    __nv_bfloat16* out = P + row * (3LL * SEQ);
    const int tid = threadIdx.x;
    const int lid = tid & 31;
    const int wid = tid >> 5;

    float v[8];
    float mx = -1e30f;
    #pragma unroll
    for (int i = 0; i < 8; i++) {
        v[i] = in[tid + i * 256];
        mx = fmaxf(mx, v[i]);
    }
    #pragma unroll
    for (int o = 16; o > 0; o >>= 1)
        mx = fmaxf(mx, __shfl_xor_sync(0xffffffffu, mx, o));

    __shared__ float smax[8], ssum[8];
    if (lid == 0) smax[wid] = mx;
    __syncthreads();
    mx = smax[0];
    #pragma unroll
    for (int w = 1; w < 8; w++) mx = fmaxf(mx, smax[w]);

    float sum = 0.0f;
    #pragma unroll
    for (int i = 0; i < 8; i++) {
        v[i] = __expf(v[i] - mx);
        sum += v[i];
    }
    #pragma unroll
    for (int o = 16; o > 0; o >>= 1)
        sum += __shfl_xor_sync(0xffffffffu, sum, o);
    if (lid == 0) ssum[wid] = sum;
    __syncthreads();
    sum = 0.0f;
    #pragma unroll
    for (int w = 0; w < 8; w++) sum += ssum[w];

    float inv = 1.0f / sum;
    #pragma unroll
    for (int i = 0; i < 8; i++) {
        float p = v[i] * inv;
        __nv_bfloat16 h = __float2bfloat16(p);
        __nv_bfloat16 l = __float2bfloat16(p - __bfloat162float(h));
        int col = tid + i * 256;
        out[col] = h;
        out[SEQ + col] = l;
        out[2 * SEQ + col] = h;
    }
}

// ---------------- launch ----------------
extern "C" void kernel_launch(void* const* d_in, const int* in_sizes, int n_in,
                              void* d_out, int out_size)
{
    const float* x  = (const float*)d_in[0];
    const float* Wq = (const float*)d_in[1];
    const float* bq = (const float*)d_in[2];
    const float* Wk = (const float*)d_in[3];
    const float* bk = (const float*)d_in[4];
    const float* Wv = (const float*)d_in[5];
    const float* bv = (const float*)d_in[6];
    const float* Wo = (const float*)d_in[7];
    const float* bo = (const float*)d_in[8];
    float* out = (float*)d_out;

    __nv_bfloat16 *xb, *Wqb, *Wkb, *Wvb, *Wob, *Qb, *Kb, *VTb, *Pb, *Ob;
    float* S;
    cudaGetSymbolAddress((void**)&xb,  g_xb);
    cudaGetSymbolAddress((void**)&Wqb, g_Wqb);
    cudaGetSymbolAddress((void**)&Wkb, g_Wkb);
    cudaGetSymbolAddress((void**)&Wvb, g_Wvb);
    cudaGetSymbolAddress((void**)&Wob, g_Wob);
    cudaGetSymbolAddress((void**)&Qb,  g_Qb);
    cudaGetSymbolAddress((void**)&Kb,  g_Kb);
    cudaGetSymbolAddress((void**)&VTb, g_VTb);
    cudaGetSymbolAddress((void**)&S,   g_S);
    cudaGetSymbolAddress((void**)&Pb,  g_Pb);
    cudaGetSymbolAddress((void**)&Ob,  g_Ob);

    cudaFuncSetAttribute(mma_gemm<0, false>, cudaFuncAttributeMaxDynamicSharedMemorySize, GEMM_SMEM);
    cudaFuncSetAttribute(mma_gemm<0, true >, cudaFuncAttributeMaxDynamicSharedMemorySize, GEMM_SMEM);
    cudaFuncSetAttribute(mma_gemm<1, false>, cudaFuncAttributeMaxDynamicSharedMemorySize, GEMM_SMEM);
    cudaFuncSetAttribute(mma_gemm<1, true >, cudaFuncAttributeMaxDynamicSharedMemorySize, GEMM_SMEM);
    cudaFuncSetAttribute(mma_gemm<2, true >, cudaFuncAttributeMaxDynamicSharedMemorySize, GEMM_SMEM);
    cudaFuncSetAttribute(mma_gemm<3, true >, cudaFuncAttributeMaxDynamicSharedMemorySize, GEMM_SMEM);

    // 1) conversions
    {
        long long tx = (long long)MTOT * EMB;
        cvt_split3<0><<<(unsigned)((tx + 255) / 256), 256>>>(x, xb, EMB, tx);
        long long tw = (long long)EMB * EMB;
        unsigned gw = (unsigned)((tw + 255) / 256);
        cvt_split3<1><<<gw, 256>>>(Wq, Wqb, EMB, tw);
        cvt_split3<1><<<gw, 256>>>(Wk, Wkb, EMB, tw);
        cvt_split3<1><<<gw, 256>>>(Wv, Wvb, EMB, tw);
        cvt_split3<1><<<gw, 256>>>(Wo, Wob, EMB, tw);
    }

    dim3 blk(256);
    const float scale = 1.0f / 32.0f;

    // 2) projections: [8192,3072] x [1024,3072]^T  -> grid (1024/256, 8192/128)
    dim3 gProj(EMB / 256, MTOT / 128, 1);
    mma_gemm<1, true><<<gProj, blk, GEMM_SMEM>>>(xb, Wqb, bq, Qb, EMB, K1, 1.0f, 0, 0, 0);
    mma_gemm<2, true><<<gProj, blk, GEMM_SMEM>>>(xb, Wkb, bk, Kb, EMB, K1, 1.0f, 0, 0, 0);
    mma_gemm<3, true><<<gProj, blk, GEMM_SMEM>>>(xb, Wvb, bv, VTb, EMB, K1, 1.0f, 0, 0, 0);

    // 3) scores = scale * Q K^T  (fp32 out)
    dim3 gScore(SEQ / 256, SEQ / 128, BATCH);
    mma_gemm<0, false><<<gScore, blk, GEMM_SMEM>>>(
        Qb, Kb, nullptr, S, SEQ, K1, scale,
        (long long)SEQ * K1, (long long)SEQ * K1, (long long)SEQ * SEQ);

    // 4) softmax -> split-A P
    softmax_split<<<BATCH * SEQ, blk>>>(S, Pb);

    // 5) O = P V
    dim3 gPV(EMB / 256, SEQ / 128, BATCH);
    mma_gemm<1, false><<<gPV, blk, GEMM_SMEM>>>(
        Pb, VTb, nullptr, Ob, EMB, K2, 1.0f,
        (long long)SEQ * K2, (long long)EMB * K2, (long long)SEQ * K1);

    // 6) out = O Wo^T + bo (fp32 out)
    mma_gemm<0, true><<<gProj, blk, GEMM_SMEM>>>(Ob, Wob, bo, out, EMB, K1, 1.0f, 0, 0, 0);
}

// round 6
// speedup vs baseline: 1.8325x; 1.8325x over previous
#include <cuda_runtime.h>
#include <cuda_bf16.h>
#include <cstdint>

#define SEQ   2048
#define EMB   1024
#define BATCH 4
#define MTOT  (BATCH * SEQ)   // 8192

#define K1 (3 * EMB)   // 3072
#define K2 (3 * SEQ)   // 6144

// ---------------- scratch (device globals; allocation-free) ----------------
__device__ __nv_bfloat16 g_xb  [(long long)MTOT * K1];
__device__ __nv_bfloat16 g_Wcat[(long long)(3 * EMB) * K1];   // [Wq;Wk;Wv] split-B
__device__ __nv_bfloat16 g_Wob [(long long)EMB * K1];
__device__ __nv_bfloat16 g_Qb  [(long long)MTOT * K1];
__device__ __nv_bfloat16 g_Kb  [(long long)MTOT * K1];
__device__ __nv_bfloat16 g_VTb [(long long)BATCH * EMB * K2];
__device__ float         g_S   [(long long)BATCH * SEQ * SEQ];
__device__ __nv_bfloat16 g_Pb  [(long long)BATCH * SEQ * K2];
__device__ __nv_bfloat16 g_Ob  [(long long)MTOT * K1];

// ---------------- helpers ----------------
__device__ __forceinline__ uint32_t smem_to_u32(const void* p) {
    uint32_t a;
    asm("{ .reg .u64 t; cvta.to.shared.u64 t, %1; cvt.u32.u64 %0, t; }" : "=r"(a) : "l"(p));
    return a;
}

#define CP_ASYNC16(dst, src) \
    asm volatile("cp.async.cg.shared.global [%0], [%1], 16;" :: "r"(dst), "l"(src))
#define CP_COMMIT() asm volatile("cp.async.commit_group;" ::: "memory")

__device__ __forceinline__ void ldmatrix_x4(uint32_t& r0, uint32_t& r1, uint32_t& r2, uint32_t& r3,
                                            uint32_t addr) {
    asm volatile("ldmatrix.sync.aligned.m8n8.x4.shared.b16 {%0,%1,%2,%3}, [%4];"
                 : "=r"(r0), "=r"(r1), "=r"(r2), "=r"(r3) : "r"(addr));
}

__device__ __forceinline__ void mma16816(float* c, uint32_t a0, uint32_t a1, uint32_t a2, uint32_t a3,
                                         uint32_t b0, uint32_t b1) {
    asm volatile("mma.sync.aligned.m16n8k16.row.col.f32.bf16.bf16.f32 "
                 "{%0,%1,%2,%3}, {%4,%5,%6,%7}, {%8,%9}, {%0,%1,%2,%3};"
                 : "+f"(c[0]), "+f"(c[1]), "+f"(c[2]), "+f"(c[3])
                 : "r"(a0), "r"(a1), "r"(a2), "r"(a3), "r"(b0), "r"(b1));
}

// ---------------- conversions ----------------
// x: fp32 [8192,1024] -> split-A [hi|lo|hi]
__global__ __launch_bounds__(256)
void cvt_x(const float* __restrict__ in, __nv_bfloat16* __restrict__ out)
{
    long long idx = (long long)blockIdx.x * blockDim.x + threadIdx.x;
    long long r = idx >> 10;
    int c = (int)(idx & 1023);
    float x = in[idx];
    __nv_bfloat16 h = __float2bfloat16(x);
    __nv_bfloat16 l = __float2bfloat16(x - __bfloat162float(h));
    long long ro = r * (long long)K1;
    out[ro + c] = h;
    out[ro + EMB + c] = l;
    out[ro + 2 * EMB + c] = h;
}

// weights: blockIdx.y selects Wq/Wk/Wv (into Wcat row offset) or Wo (into Wob).
// All split-B [hi|hi|lo].
__global__ __launch_bounds__(256)
void cvt_weights(const float* __restrict__ Wq, const float* __restrict__ Wk,
                 const float* __restrict__ Wv, const float* __restrict__ Wo,
                 __nv_bfloat16* __restrict__ Wcat, __nv_bfloat16* __restrict__ Wob)
{
    int w = blockIdx.y;
    const float* src = (w == 0) ? Wq : (w == 1) ? Wk : (w == 2) ? Wv : Wo;
    long long idx = (long long)blockIdx.x * blockDim.x + threadIdx.x;
    long long r = idx >> 10;
    int c = (int)(idx & 1023);
    float x = src[idx];
    __nv_bfloat16 h = __float2bfloat16(x);
    __nv_bfloat16 l = __float2bfloat16(x - __bfloat162float(h));
    __nv_bfloat16* out = (w < 3) ? (Wcat + (long long)w * EMB * K1) : Wob;
    long long ro = r * (long long)K1;
    out[ro + c] = h;
    out[ro + EMB + c] = h;
    out[ro + 2 * EMB + c] = l;
}

// ---------------- epilogue writers ----------------
__device__ __forceinline__ void write_splitA(__nv_bfloat16* O, int gm, int gn, int Nl,
                                             float v0, float v1) {
    long long ro = (long long)gm * (3LL * Nl);
    __nv_bfloat16 h0 = __float2bfloat16(v0);
    __nv_bfloat16 l0 = __float2bfloat16(v0 - __bfloat162float(h0));
    __nv_bfloat16 h1 = __float2bfloat16(v1);
    __nv_bfloat16 l1 = __float2bfloat16(v1 - __bfloat162float(h1));
    *(__nv_bfloat162*)&O[ro + gn] = __nv_bfloat162(h0, h1);
    *(__nv_bfloat162*)&O[ro + Nl + gn] = __nv_bfloat162(l0, l1);
    *(__nv_bfloat162*)&O[ro + 2LL * Nl + gn] = __nv_bfloat162(h0, h1);
}
__device__ __forceinline__ void write_splitB(__nv_bfloat16* O, int gm, int gn, int Nl,
                                             float v0, float v1) {
    long long ro = (long long)gm * (3LL * Nl);
    __nv_bfloat16 h0 = __float2bfloat16(v0);
    __nv_bfloat16 l0 = __float2bfloat16(v0 - __bfloat162float(h0));
    __nv_bfloat16 h1 = __float2bfloat16(v1);
    __nv_bfloat16 l1 = __float2bfloat16(v1 - __bfloat162float(h1));
    *(__nv_bfloat162*)&O[ro + gn] = __nv_bfloat162(h0, h1);
    *(__nv_bfloat162*)&O[ro + Nl + gn] = __nv_bfloat162(h0, h1);
    *(__nv_bfloat162*)&O[ro + 2LL * Nl + gn] = __nv_bfloat162(l0, l1);
}
__device__ __forceinline__ void write_splitBT(__nv_bfloat16* O, int gm, int gn, int Nl,
                                              float v0, float v1) {
    // O[b][n][3*SEQ]: [s]=hi, [SEQ+s]=hi, [2SEQ+s]=lo
    int b = gm >> 11;
    int sdx = gm & (SEQ - 1);
    #pragma unroll
    for (int e = 0; e < 2; e++) {
        float v = e ? v1 : v0;
        int n = gn + e;
        __nv_bfloat16 h = __float2bfloat16(v);
        __nv_bfloat16 l = __float2bfloat16(v - __bfloat162float(h));
        long long base = (long long)b * Nl * (3LL * SEQ) + (long long)n * (3LL * SEQ) + sdx;
        O[base] = h;
        O[base + SEQ] = h;
        O[base + 2 * SEQ] = l;
    }
}

// ---------------- HMMA GEMM: C = alpha * A * B^T (+bias) ----------------
// Block 128x128, BK=64, NSTAGE=3, 8 warps (4M x 2N), warp tile 32x64.
// Single __syncthreads per chunk.
// EPI: 0=fp32 out (O0,b0); 1=split-A out (O0); 4=fused QKV (region by n0>>10)
#define BK      64
#define NSTAGE  3
#define STAGE_BYTES 32768
#define GEMM_SMEM (NSTAGE * STAGE_BYTES)

template <int EPI, bool HAS_BIAS>
__global__ __launch_bounds__(256, 2)
void mma_gemm(const __nv_bfloat16* __restrict__ A, const __nv_bfloat16* __restrict__ B,
              const float* __restrict__ b0, const float* __restrict__ b1,
              const float* __restrict__ b2,
              void* __restrict__ O0, void* __restrict__ O1, void* __restrict__ O2,
              int Nlog, int Ktot, float alpha,
              long long sA, long long sB, long long sO)
{
    extern __shared__ __align__(1024) char smem[];
    const uint32_t smem_base = smem_to_u32(smem);
    const int tid = threadIdx.x;
    const int wid = tid >> 5;
    const int lane = tid & 31;
    const int warp_m = wid & 3;
    const int warp_n = wid >> 2;

    A += (long long)blockIdx.z * sA;
    B += (long long)blockIdx.z * sB;

    const int m0 = blockIdx.y * 128;
    const int n0 = blockIdx.x * 128;

    const int nchunks = Ktot / BK;

    auto load_stage = [&](int chunk, int s) {
        uint32_t sa = smem_base + s * STAGE_BYTES;
        uint32_t sb = sa + 16384;
        long long k0 = (long long)chunk * BK;
        #pragma unroll
        for (int t = 0; t < 4; t++) {
            int idx = tid + t * 256;
            int r = idx >> 3, c = idx & 7;
            uint32_t off = (uint32_t)((r * 8 + (c ^ (r & 7))) * 16);
            CP_ASYNC16(sa + off, (const void*)(A + (long long)(m0 + r) * Ktot + k0 + c * 8));
            CP_ASYNC16(sb + off, (const void*)(B + (long long)(n0 + r) * Ktot + k0 + c * 8));
        }
        CP_COMMIT();
    };

    float acc[2][8][4];
    #pragma unroll
    for (int mi = 0; mi < 2; mi++)
        #pragma unroll
        for (int ni = 0; ni < 8; ni++)
            #pragma unroll
            for (int r = 0; r < 4; r++)
                acc[mi][ni][r] = 0.0f;

    load_stage(0, 0);
    load_stage(1, 1);

    const int a_row = (lane & 15);
    const int a_half = lane >> 4;
    const int b_noff = (lane & 7) + ((lane & 16) ? 8 : 0);
    const int b_kg = (lane & 8) ? 1 : 0;

    for (int i = 0; i < nchunks; i++) {
        if (i + 1 < nchunks) {
            asm volatile("cp.async.wait_group 1;" ::: "memory");
        } else {
            asm volatile("cp.async.wait_group 0;" ::: "memory");
        }
        __syncthreads();

        if (i + 2 < nchunks) load_stage(i + 2, (i + 2) % NSTAGE);

        const int s = i % NSTAGE;
        const uint32_t sa = smem_base + s * STAGE_BYTES;
        const uint32_t sb = sa + 16384;

        #pragma unroll
        for (int kk = 0; kk < 4; kk++) {
            uint32_t af[2][4];
            #pragma unroll
            for (int mi = 0; mi < 2; mi++) {
                int row = warp_m * 32 + mi * 16 + a_row;
                int g = (kk * 2 + a_half) ^ (row & 7);
                ldmatrix_x4(af[mi][0], af[mi][1], af[mi][2], af[mi][3],
                            sa + (uint32_t)((row * 8 + g) * 16));
            }
            uint32_t bf[4][4];
            #pragma unroll
            for (int nt = 0; nt < 4; nt++) {
                int row = warp_n * 64 + nt * 16 + b_noff;
                int g = (kk * 2 + b_kg) ^ (row & 7);
                ldmatrix_x4(bf[nt][0], bf[nt][1], bf[nt][2], bf[nt][3],
                            sb + (uint32_t)((row * 8 + g) * 16));
            }
            #pragma unroll
            for (int mi = 0; mi < 2; mi++)
                #pragma unroll
                for (int ni = 0; ni < 8; ni++) {
                    int nt = ni >> 1;
                    uint32_t bb0 = (ni & 1) ? bf[nt][2] : bf[nt][0];
                    uint32_t bb1 = (ni & 1) ? bf[nt][3] : bf[nt][1];
                    mma16816(acc[mi][ni], af[mi][0], af[mi][1], af[mi][2], af[mi][3], bb0, bb1);
                }
        }
    }

    // ---- epilogue ----
    const int rbase = m0 + warp_m * 32 + (lane >> 2);
    const int cbase = n0 + warp_n * 64 + (lane & 3) * 2;

    // fused-QKV region select (EPI==4)
    int region = 0;
    const float* biasp = b0;
    __nv_bfloat16* Oq = (__nv_bfloat16*)O0;
    if (EPI == 4) {
        region = n0 >> 10;
        biasp = (region == 0) ? b0 : (region == 1) ? b1 : b2;
        Oq = (region == 0) ? (__nv_bfloat16*)O0
           : (region == 1) ? (__nv_bfloat16*)O1 : (__nv_bfloat16*)O2;
    }

    #pragma unroll
    for (int mi = 0; mi < 2; mi++) {
        #pragma unroll
        for (int ni = 0; ni < 8; ni++) {
            #pragma unroll
            for (int half = 0; half < 2; half++) {
                int gm = rbase + mi * 16 + half * 8;
                int gn = cbase + ni * 8;
                float v0 = acc[mi][ni][half * 2 + 0] * alpha;
                float v1 = acc[mi][ni][half * 2 + 1] * alpha;
                if (EPI == 0) {
                    if (HAS_BIAS) { v0 += b0[gn]; v1 += b0[gn + 1]; }
                    float* O = (float*)O0 + (long long)blockIdx.z * sO;
                    *(float2*)&O[(long long)gm * Nlog + gn] = make_float2(v0, v1);
                } else if (EPI == 1) {
                    if (HAS_BIAS) { v0 += b0[gn]; v1 += b0[gn + 1]; }
                    __nv_bfloat16* O = (__nv_bfloat16*)O0 + (long long)blockIdx.z * sO;
                    write_splitA(O, gm, gn, Nlog, v0, v1);
                } else { // EPI == 4
                    int nl = gn & (EMB - 1);
                    if (HAS_BIAS) { v0 += biasp[nl]; v1 += biasp[nl + 1]; }
                    if (region == 0)      write_splitA (Oq, gm, nl, EMB, v0, v1);
                    else if (region == 1) write_splitB (Oq, gm, nl, EMB, v0, v1);
                    else                  write_splitBT(Oq, gm, nl, EMB, v0, v1);
                }
            }
        }
    }
}

// ---------------- softmax (fp32 in) -> split-A bf16 P ----------------
__global__ __launch_bounds__(256)
void softmax_split(const float* __restrict__ S, __nv_bfloat16* __restrict__ P)
{
    long long row = blockIdx.x;
    const float* in = S + row * SEQ;
    __nv_bfloat16* out = P + row * (3LL * SEQ);
    const int tid = threadIdx.x;
    const int lid = tid & 31;
    const int wid = tid >> 5;

    float v[8];
    float mx = -1e30f;
    #pragma unroll
    for (int i = 0; i < 8; i++) {
        v[i] = in[tid + i * 256];
        mx = fmaxf(mx, v[i]);
    }
    #pragma unroll
    for (int o = 16; o > 0; o >>= 1)
        mx = fmaxf(mx, __shfl_xor_sync(0xffffffffu, mx, o));

    __shared__ float smax[8], ssum[8];
    if (lid == 0) smax[wid] = mx;
    __syncthreads();
    mx = smax[0];
    #pragma unroll
    for (int w = 1; w < 8; w++) mx = fmaxf(mx, smax[w]);

    float sum = 0.0f;
    #pragma unroll
    for (int i = 0; i < 8; i++) {
        v[i] = __expf(v[i] - mx);
        sum += v[i];
    }
    #pragma unroll
    for (int o = 16; o > 0; o >>= 1)
        sum += __shfl_xor_sync(0xffffffffu, sum, o);
    if (lid == 0) ssum[wid] = sum;
    __syncthreads();
    sum = 0.0f;
    #pragma unroll
    for (int w = 0; w < 8; w++) sum += ssum[w];

    float inv = 1.0f / sum;
    #pragma unroll
    for (int i = 0; i < 8; i++) {
        float p = v[i] * inv;
        __nv_bfloat16 h = __float2bfloat16(p);
        __nv_bfloat16 l = __float2bfloat16(p - __bfloat162float(h));
        int col = tid + i * 256;
        out[col] = h;
        out[SEQ + col] = l;
        out[2 * SEQ + col] = h;
    }
}

// ---------------- launch ----------------
extern "C" void kernel_launch(void* const* d_in, const int* in_sizes, int n_in,
                              void* d_out, int out_size)
{
    const float* x  = (const float*)d_in[0];
    const float* Wq = (const float*)d_in[1];
    const float* bq = (const float*)d_in[2];
    const float* Wk = (const float*)d_in[3];
    const float* bk = (const float*)d_in[4];
    const float* Wv = (const float*)d_in[5];
    const float* bv = (const float*)d_in[6];
    const float* Wo = (const float*)d_in[7];
    const float* bo = (const float*)d_in[8];
    float* out = (float*)d_out;

    __nv_bfloat16 *xb, *Wcat, *Wob, *Qb, *Kb, *VTb, *Pb, *Ob;
    float* S;
    cudaGetSymbolAddress((void**)&xb,   g_xb);
    cudaGetSymbolAddress((void**)&Wcat, g_Wcat);
    cudaGetSymbolAddress((void**)&Wob,  g_Wob);
    cudaGetSymbolAddress((void**)&Qb,   g_Qb);
    cudaGetSymbolAddress((void**)&Kb,   g_Kb);
    cudaGetSymbolAddress((void**)&VTb,  g_VTb);
    cudaGetSymbolAddress((void**)&S,    g_S);
    cudaGetSymbolAddress((void**)&Pb,   g_Pb);
    cudaGetSymbolAddress((void**)&Ob,   g_Ob);

    cudaFuncSetAttribute(mma_gemm<0, false>, cudaFuncAttributeMaxDynamicSharedMemorySize, GEMM_SMEM);
    cudaFuncSetAttribute(mma_gemm<0, true >, cudaFuncAttributeMaxDynamicSharedMemorySize, GEMM_SMEM);
    cudaFuncSetAttribute(mma_gemm<1, false>, cudaFuncAttributeMaxDynamicSharedMemorySize, GEMM_SMEM);
    cudaFuncSetAttribute(mma_gemm<4, true >, cudaFuncAttributeMaxDynamicSharedMemorySize, GEMM_SMEM);

    dim3 blk(256);
    const float scale = 1.0f / 32.0f;

    // 1) conversions (2 launches)
    cvt_x<<<(unsigned)(((long long)MTOT * EMB) / 256), 256>>>(x, xb);
    {
        dim3 gw((unsigned)(((long long)EMB * EMB) / 256), 4);
        cvt_weights<<<gw, 256>>>(Wq, Wk, Wv, Wo, Wcat, Wob);
    }

    // 2) fused QKV projection: [8192,3072] x [3072,3072]^T
    dim3 gQKV(3 * EMB / 128, MTOT / 128, 1);   // (24, 64)
    mma_gemm<4, true><<<gQKV, blk, GEMM_SMEM>>>(
        xb, Wcat, bq, bk, bv, Qb, Kb, VTb, EMB, K1, 1.0f, 0, 0, 0);

    // 3) scores = scale * Q K^T (fp32)
    dim3 gScore(SEQ / 128, SEQ / 128, BATCH);
    mma_gemm<0, false><<<gScore, blk, GEMM_SMEM>>>(
        Qb, Kb, nullptr, nullptr, nullptr, S, nullptr, nullptr, SEQ, K1, scale,
        (long long)SEQ * K1, (long long)SEQ * K1, (long long)SEQ * SEQ);

    // 4) softmax -> split-A P
    softmax_split<<<BATCH * SEQ, blk>>>(S, Pb);

    // 5) O = P V
    dim3 gPV(EMB / 128, SEQ / 128, BATCH);
    mma_gemm<1, false><<<gPV, blk, GEMM_SMEM>>>(
        Pb, VTb, nullptr, nullptr, nullptr, Ob, nullptr, nullptr, EMB, K2, 1.0f,
        (long long)SEQ * K2, (long long)EMB * K2, (long long)SEQ * K1);

    // 6) out = O Wo^T + bo (fp32)
    dim3 gOut(EMB / 128, MTOT / 128, 1);
    mma_gemm<0, true><<<gOut, blk, GEMM_SMEM>>>(
        Ob, Wob, bo, nullptr, nullptr, out, nullptr, nullptr, EMB, K1, 1.0f, 0, 0, 0);
}

// round 7
// speedup vs baseline: 1.8645x; 1.0174x over previous
#include <cuda_runtime.h>
#include <cuda_bf16.h>
#include <cstdint>

#define SEQ   2048
#define EMB   1024
#define BATCH 4
#define MTOT  (BATCH * SEQ)   // 8192

#define K1 (3 * EMB)   // 3072
#define K2 (3 * SEQ)   // 6144

// ---------------- scratch (device globals; allocation-free) ----------------
__device__ __nv_bfloat16 g_xb  [(long long)MTOT * K1];
__device__ __nv_bfloat16 g_Wcat[(long long)(3 * EMB) * K1];   // [Wq;Wk;Wv] split-B
__device__ __nv_bfloat16 g_Wob [(long long)EMB * K1];
__device__ __nv_bfloat16 g_Qb  [(long long)MTOT * K1];
__device__ __nv_bfloat16 g_Kb  [(long long)MTOT * K1];
__device__ __nv_bfloat16 g_VTb [(long long)BATCH * EMB * K2];
__device__ float         g_S   [(long long)BATCH * SEQ * SEQ];
__device__ __nv_bfloat16 g_Pb  [(long long)BATCH * SEQ * K2];
__device__ __nv_bfloat16 g_Ob  [(long long)MTOT * K1];

// ---------------- helpers ----------------
__device__ __forceinline__ uint32_t smem_to_u32(const void* p) {
    uint32_t a;
    asm("{ .reg .u64 t; cvta.to.shared.u64 t, %1; cvt.u32.u64 %0, t; }" : "=r"(a) : "l"(p));
    return a;
}

#define CP_ASYNC16(dst, src) \
    asm volatile("cp.async.cg.shared.global [%0], [%1], 16;" :: "r"(dst), "l"(src))
#define CP_COMMIT() asm volatile("cp.async.commit_group;" ::: "memory")

__device__ __forceinline__ void ldmatrix_x4(uint32_t& r0, uint32_t& r1, uint32_t& r2, uint32_t& r3,
                                            uint32_t addr) {
    asm volatile("ldmatrix.sync.aligned.m8n8.x4.shared.b16 {%0,%1,%2,%3}, [%4];"
                 : "=r"(r0), "=r"(r1), "=r"(r2), "=r"(r3) : "r"(addr));
}

__device__ __forceinline__ void mma16816(float* c, uint32_t a0, uint32_t a1, uint32_t a2, uint32_t a3,
                                         uint32_t b0, uint32_t b1) {
    asm volatile("mma.sync.aligned.m16n8k16.row.col.f32.bf16.bf16.f32 "
                 "{%0,%1,%2,%3}, {%4,%5,%6,%7}, {%8,%9}, {%0,%1,%2,%3};"
                 : "+f"(c[0]), "+f"(c[1]), "+f"(c[2]), "+f"(c[3])
                 : "r"(a0), "r"(a1), "r"(a2), "r"(a3), "r"(b0), "r"(b1));
}

// pack 8 floats into uint4 of hi-bf16 and uint4 of lo-bf16
__device__ __forceinline__ void split8(const float* v, uint4& hi, uint4& lo) {
    uint32_t h[4], l[4];
    #pragma unroll
    for (int i = 0; i < 4; i++) {
        float a = v[2 * i], b = v[2 * i + 1];
        __nv_bfloat16 ha = __float2bfloat16(a);
        __nv_bfloat16 hb = __float2bfloat16(b);
        __nv_bfloat16 la = __float2bfloat16(a - __bfloat162float(ha));
        __nv_bfloat16 lb = __float2bfloat16(b - __bfloat162float(hb));
        __nv_bfloat162 hp(ha, hb), lp(la, lb);
        h[i] = *(uint32_t*)&hp;
        l[i] = *(uint32_t*)&lp;
    }
    hi = make_uint4(h[0], h[1], h[2], h[3]);
    lo = make_uint4(l[0], l[1], l[2], l[3]);
}

// ---------------- conversions (8 elems/thread, 16B stores) ----------------
// x: fp32 [8192,1024] -> split-A [hi|lo|hi]
__global__ __launch_bounds__(256)
void cvt_x(const float* __restrict__ in, __nv_bfloat16* __restrict__ out)
{
    long long idx = (long long)blockIdx.x * blockDim.x + threadIdx.x;  // 8-elem units
    long long r = idx >> 7;           // EMB/8 = 128 units per row
    int c8 = (int)(idx & 127);
    const float4* src = (const float4*)(in + r * EMB + c8 * 8);
    float v[8];
    float4 f0 = src[0], f1 = src[1];
    v[0]=f0.x; v[1]=f0.y; v[2]=f0.z; v[3]=f0.w;
    v[4]=f1.x; v[5]=f1.y; v[6]=f1.z; v[7]=f1.w;
    uint4 hi, lo;
    split8(v, hi, lo);
    long long ro = r * (long long)K1 + c8 * 8;
    *(uint4*)(out + ro)           = hi;
    *(uint4*)(out + ro + EMB)     = lo;
    *(uint4*)(out + ro + 2 * EMB) = hi;
}

// weights -> split-B [hi|hi|lo]; blockIdx.y selects Wq/Wk/Wv (Wcat) or Wo (Wob)
__global__ __launch_bounds__(256)
void cvt_weights(const float* __restrict__ Wq, const float* __restrict__ Wk,
                 const float* __restrict__ Wv, const float* __restrict__ Wo,
                 __nv_bfloat16* __restrict__ Wcat, __nv_bfloat16* __restrict__ Wob)
{
    int w = blockIdx.y;
    const float* src = (w == 0) ? Wq : (w == 1) ? Wk : (w == 2) ? Wv : Wo;
    long long idx = (long long)blockIdx.x * blockDim.x + threadIdx.x;
    long long r = idx >> 7;
    int c8 = (int)(idx & 127);
    const float4* s4 = (const float4*)(src + r * EMB + c8 * 8);
    float v[8];
    float4 f0 = s4[0], f1 = s4[1];
    v[0]=f0.x; v[1]=f0.y; v[2]=f0.z; v[3]=f0.w;
    v[4]=f1.x; v[5]=f1.y; v[6]=f1.z; v[7]=f1.w;
    uint4 hi, lo;
    split8(v, hi, lo);
    __nv_bfloat16* out = (w < 3) ? (Wcat + (long long)w * EMB * K1) : Wob;
    long long ro = r * (long long)K1 + c8 * 8;
    *(uint4*)(out + ro)           = hi;
    *(uint4*)(out + ro + EMB)     = hi;
    *(uint4*)(out + ro + 2 * EMB) = lo;
}

// ---------------- epilogue writers ----------------
__device__ __forceinline__ void write_splitA(__nv_bfloat16* O, int gm, int gn, int Nl,
                                             float v0, float v1) {
    long long ro = (long long)gm * (3LL * Nl);
    __nv_bfloat16 h0 = __float2bfloat16(v0);
    __nv_bfloat16 l0 = __float2bfloat16(v0 - __bfloat162float(h0));
    __nv_bfloat16 h1 = __float2bfloat16(v1);
    __nv_bfloat16 l1 = __float2bfloat16(v1 - __bfloat162float(h1));
    *(__nv_bfloat162*)&O[ro + gn] = __nv_bfloat162(h0, h1);
    *(__nv_bfloat162*)&O[ro + Nl + gn] = __nv_bfloat162(l0, l1);
    *(__nv_bfloat162*)&O[ro + 2LL * Nl + gn] = __nv_bfloat162(h0, h1);
}
__device__ __forceinline__ void write_splitB(__nv_bfloat16* O, int gm, int gn, int Nl,
                                             float v0, float v1) {
    long long ro = (long long)gm * (3LL * Nl);
    __nv_bfloat16 h0 = __float2bfloat16(v0);
    __nv_bfloat16 l0 = __float2bfloat16(v0 - __bfloat162float(h0));
    __nv_bfloat16 h1 = __float2bfloat16(v1);
    __nv_bfloat16 l1 = __float2bfloat16(v1 - __bfloat162float(h1));
    *(__nv_bfloat162*)&O[ro + gn] = __nv_bfloat162(h0, h1);
    *(__nv_bfloat162*)&O[ro + Nl + gn] = __nv_bfloat162(h0, h1);
    *(__nv_bfloat162*)&O[ro + 2LL * Nl + gn] = __nv_bfloat162(l0, l1);
}
__device__ __forceinline__ void write_splitBT(__nv_bfloat16* O, int gm, int gn, int Nl,
                                              float v0, float v1) {
    int b = gm >> 11;
    int sdx = gm & (SEQ - 1);
    #pragma unroll
    for (int e = 0; e < 2; e++) {
        float v = e ? v1 : v0;
        int n = gn + e;
        __nv_bfloat16 h = __float2bfloat16(v);
        __nv_bfloat16 l = __float2bfloat16(v - __bfloat162float(h));
        long long base = (long long)b * Nl * (3LL * SEQ) + (long long)n * (3LL * SEQ) + sdx;
        O[base] = h;
        O[base + SEQ] = h;
        O[base + 2 * SEQ] = l;
    }
}

// ---------------- HMMA GEMM (unchanged from R6) ----------------
#define BK      64
#define NSTAGE  3
#define STAGE_BYTES 32768
#define GEMM_SMEM (NSTAGE * STAGE_BYTES)

template <int EPI, bool HAS_BIAS>
__global__ __launch_bounds__(256, 2)
void mma_gemm(const __nv_bfloat16* __restrict__ A, const __nv_bfloat16* __restrict__ B,
              const float* __restrict__ b0, const float* __restrict__ b1,
              const float* __restrict__ b2,
              void* __restrict__ O0, void* __restrict__ O1, void* __restrict__ O2,
              int Nlog, int Ktot, float alpha,
              long long sA, long long sB, long long sO)
{
    extern __shared__ __align__(1024) char smem[];
    const uint32_t smem_base = smem_to_u32(smem);
    const int tid = threadIdx.x;
    const int wid = tid >> 5;
    const int lane = tid & 31;
    const int warp_m = wid & 3;
    const int warp_n = wid >> 2;

    A += (long long)blockIdx.z * sA;
    B += (long long)blockIdx.z * sB;

    const int m0 = blockIdx.y * 128;
    const int n0 = blockIdx.x * 128;

    const int nchunks = Ktot / BK;

    auto load_stage = [&](int chunk, int s) {
        uint32_t sa = smem_base + s * STAGE_BYTES;
        uint32_t sb = sa + 16384;
        long long k0 = (long long)chunk * BK;
        #pragma unroll
        for (int t = 0; t < 4; t++) {
            int idx = tid + t * 256;
            int r = idx >> 3, c = idx & 7;
            uint32_t off = (uint32_t)((r * 8 + (c ^ (r & 7))) * 16);
            CP_ASYNC16(sa + off, (const void*)(A + (long long)(m0 + r) * Ktot + k0 + c * 8));
            CP_ASYNC16(sb + off, (const void*)(B + (long long)(n0 + r) * Ktot + k0 + c * 8));
        }
        CP_COMMIT();
    };

    float acc[2][8][4];
    #pragma unroll
    for (int mi = 0; mi < 2; mi++)
        #pragma unroll
        for (int ni = 0; ni < 8; ni++)
            #pragma unroll
            for (int r = 0; r < 4; r++)
                acc[mi][ni][r] = 0.0f;

    load_stage(0, 0);
    load_stage(1, 1);

    const int a_row = (lane & 15);
    const int a_half = lane >> 4;
    const int b_noff = (lane & 7) + ((lane & 16) ? 8 : 0);
    const int b_kg = (lane & 8) ? 1 : 0;

    for (int i = 0; i < nchunks; i++) {
        if (i + 1 < nchunks) {
            asm volatile("cp.async.wait_group 1;" ::: "memory");
        } else {
            asm volatile("cp.async.wait_group 0;" ::: "memory");
        }
        __syncthreads();

        if (i + 2 < nchunks) load_stage(i + 2, (i + 2) % NSTAGE);

        const int s = i % NSTAGE;
        const uint32_t sa = smem_base + s * STAGE_BYTES;
        const uint32_t sb = sa + 16384;

        #pragma unroll
        for (int kk = 0; kk < 4; kk++) {
            uint32_t af[2][4];
            #pragma unroll
            for (int mi = 0; mi < 2; mi++) {
                int row = warp_m * 32 + mi * 16 + a_row;
                int g = (kk * 2 + a_half) ^ (row & 7);
                ldmatrix_x4(af[mi][0], af[mi][1], af[mi][2], af[mi][3],
                            sa + (uint32_t)((row * 8 + g) * 16));
            }
            uint32_t bf[4][4];
            #pragma unroll
            for (int nt = 0; nt < 4; nt++) {
                int row = warp_n * 64 + nt * 16 + b_noff;
                int g = (kk * 2 + b_kg) ^ (row & 7);
                ldmatrix_x4(bf[nt][0], bf[nt][1], bf[nt][2], bf[nt][3],
                            sb + (uint32_t)((row * 8 + g) * 16));
            }
            #pragma unroll
            for (int mi = 0; mi < 2; mi++)
                #pragma unroll
                for (int ni = 0; ni < 8; ni++) {
                    int nt = ni >> 1;
                    uint32_t bb0 = (ni & 1) ? bf[nt][2] : bf[nt][0];
                    uint32_t bb1 = (ni & 1) ? bf[nt][3] : bf[nt][1];
                    mma16816(acc[mi][ni], af[mi][0], af[mi][1], af[mi][2], af[mi][3], bb0, bb1);
                }
        }
    }

    // ---- epilogue ----
    const int rbase = m0 + warp_m * 32 + (lane >> 2);
    const int cbase = n0 + warp_n * 64 + (lane & 3) * 2;

    int region = 0;
    const float* biasp = b0;
    __nv_bfloat16* Oq = (__nv_bfloat16*)O0;
    if (EPI == 4) {
        region = n0 >> 10;
        biasp = (region == 0) ? b0 : (region == 1) ? b1 : b2;
        Oq = (region == 0) ? (__nv_bfloat16*)O0
           : (region == 1) ? (__nv_bfloat16*)O1 : (__nv_bfloat16*)O2;
    }

    #pragma unroll
    for (int mi = 0; mi < 2; mi++) {
        #pragma unroll
        for (int ni = 0; ni < 8; ni++) {
            #pragma unroll
            for (int half = 0; half < 2; half++) {
                int gm = rbase + mi * 16 + half * 8;
                int gn = cbase + ni * 8;
                float v0 = acc[mi][ni][half * 2 + 0] * alpha;
                float v1 = acc[mi][ni][half * 2 + 1] * alpha;
                if (EPI == 0) {
                    if (HAS_BIAS) { v0 += b0[gn]; v1 += b0[gn + 1]; }
                    float* O = (float*)O0 + (long long)blockIdx.z * sO;
                    *(float2*)&O[(long long)gm * Nlog + gn] = make_float2(v0, v1);
                } else if (EPI == 1) {
                    if (HAS_BIAS) { v0 += b0[gn]; v1 += b0[gn + 1]; }
                    __nv_bfloat16* O = (__nv_bfloat16*)O0 + (long long)blockIdx.z * sO;
                    write_splitA(O, gm, gn, Nlog, v0, v1);
                } else { // EPI == 4
                    int nl = gn & (EMB - 1);
                    if (HAS_BIAS) { v0 += biasp[nl]; v1 += biasp[nl + 1]; }
                    if (region == 0)      write_splitA (Oq, gm, nl, EMB, v0, v1);
                    else if (region == 1) write_splitB (Oq, gm, nl, EMB, v0, v1);
                    else                  write_splitBT(Oq, gm, nl, EMB, v0, v1);
                }
            }
        }
    }
}

// ---------------- softmax: fp32 in -> split-A bf16 P, vectorized ----------------
__global__ __launch_bounds__(256)
void softmax_split(const float* __restrict__ S, __nv_bfloat16* __restrict__ P)
{
    long long row = blockIdx.x;
    const float4* in4 = (const float4*)(S + row * SEQ);
    __nv_bfloat16* out = P + row * (3LL * SEQ);
    const int tid = threadIdx.x;
    const int lid = tid & 31;
    const int wid = tid >> 5;

    // thread t handles cols [8t, 8t+7]
    float v[8];
    {
        float4 f0 = in4[tid * 2];
        float4 f1 = in4[tid * 2 + 1];
        v[0]=f0.x; v[1]=f0.y; v[2]=f0.z; v[3]=f0.w;
        v[4]=f1.x; v[5]=f1.y; v[6]=f1.z; v[7]=f1.w;
    }
    float mx = v[0];
    #pragma unroll
    for (int i = 1; i < 8; i++) mx = fmaxf(mx, v[i]);
    #pragma unroll
    for (int o = 16; o > 0; o >>= 1)
        mx = fmaxf(mx, __shfl_xor_sync(0xffffffffu, mx, o));

    __shared__ float smax[8], ssum[8];
    if (lid == 0) smax[wid] = mx;
    __syncthreads();
    mx = smax[0];
    #pragma unroll
    for (int w = 1; w < 8; w++) mx = fmaxf(mx, smax[w]);

    float sum = 0.0f;
    #pragma unroll
    for (int i = 0; i < 8; i++) {
        v[i] = __expf(v[i] - mx);
        sum += v[i];
    }
    #pragma unroll
    for (int o = 16; o > 0; o >>= 1)
        sum += __shfl_xor_sync(0xffffffffu, sum, o);
    if (lid == 0) ssum[wid] = sum;
    __syncthreads();
    sum = 0.0f;
    #pragma unroll
    for (int w = 0; w < 8; w++) sum += ssum[w];

    float inv = 1.0f / sum;
    #pragma unroll
    for (int i = 0; i < 8; i++) v[i] *= inv;

    uint4 hi, lo;
    split8(v, hi, lo);
    int col = tid * 8;
    *(uint4*)(out + col)           = hi;   // hi
    *(uint4*)(out + SEQ + col)     = lo;   // lo
    *(uint4*)(out + 2 * SEQ + col) = hi;   // hi
}

// ---------------- launch ----------------
extern "C" void kernel_launch(void* const* d_in, const int* in_sizes, int n_in,
                              void* d_out, int out_size)
{
    const float* x  = (const float*)d_in[0];
    const float* Wq = (const float*)d_in[1];
    const float* bq = (const float*)d_in[2];
    const float* Wk = (const float*)d_in[3];
    const float* bk = (const float*)d_in[4];
    const float* Wv = (const float*)d_in[5];
    const float* bv = (const float*)d_in[6];
    const float* Wo = (const float*)d_in[7];
    const float* bo = (const float*)d_in[8];
    float* out = (float*)d_out;

    __nv_bfloat16 *xb, *Wcat, *Wob, *Qb, *Kb, *VTb, *Pb, *Ob;
    float* S;
    cudaGetSymbolAddress((void**)&xb,   g_xb);
    cudaGetSymbolAddress((void**)&Wcat, g_Wcat);
    cudaGetSymbolAddress((void**)&Wob,  g_Wob);
    cudaGetSymbolAddress((void**)&Qb,   g_Qb);
    cudaGetSymbolAddress((void**)&Kb,   g_Kb);
    cudaGetSymbolAddress((void**)&VTb,  g_VTb);
    cudaGetSymbolAddress((void**)&S,    g_S);
    cudaGetSymbolAddress((void**)&Pb,   g_Pb);
    cudaGetSymbolAddress((void**)&Ob,   g_Ob);

    cudaFuncSetAttribute(mma_gemm<0, false>, cudaFuncAttributeMaxDynamicSharedMemorySize, GEMM_SMEM);
    cudaFuncSetAttribute(mma_gemm<0, true >, cudaFuncAttributeMaxDynamicSharedMemorySize, GEMM_SMEM);
    cudaFuncSetAttribute(mma_gemm<1, false>, cudaFuncAttributeMaxDynamicSharedMemorySize, GEMM_SMEM);
    cudaFuncSetAttribute(mma_gemm<4, true >, cudaFuncAttributeMaxDynamicSharedMemorySize, GEMM_SMEM);

    dim3 blk(256);
    const float scale = 1.0f / 32.0f;

    // 1) conversions (vectorized, 8 elems/thread)
    cvt_x<<<(unsigned)(((long long)MTOT * EMB / 8) / 256), 256>>>(x, xb);
    {
        dim3 gw((unsigned)(((long long)EMB * EMB / 8) / 256), 4);
        cvt_weights<<<gw, 256>>>(Wq, Wk, Wv, Wo, Wcat, Wob);
    }

    // 2) fused QKV projection: [8192,3072] x [3072,3072]^T
    dim3 gQKV(3 * EMB / 128, MTOT / 128, 1);
    mma_gemm<4, true><<<gQKV, blk, GEMM_SMEM>>>(
        xb, Wcat, bq, bk, bv, Qb, Kb, VTb, EMB, K1, 1.0f, 0, 0, 0);

    // 3) scores = scale * Q K^T (fp32)
    dim3 gScore(SEQ / 128, SEQ / 128, BATCH);
    mma_gemm<0, false><<<gScore, blk, GEMM_SMEM>>>(
        Qb, Kb, nullptr, nullptr, nullptr, S, nullptr, nullptr, SEQ, K1, scale,
        (long long)SEQ * K1, (long long)SEQ * K1, (long long)SEQ * SEQ);

    // 4) softmax -> split-A P
    softmax_split<<<BATCH * SEQ, blk>>>(S, Pb);

    // 5) O = P V
    dim3 gPV(EMB / 128, SEQ / 128, BATCH);
    mma_gemm<1, false><<<gPV, blk, GEMM_SMEM>>>(
        Pb, VTb, nullptr, nullptr, nullptr, Ob, nullptr, nullptr, EMB, K2, 1.0f,
        (long long)SEQ * K2, (long long)EMB * K2, (long long)SEQ * K1);

    // 6) out = O Wo^T + bo (fp32)
    dim3 gOut(EMB / 128, MTOT / 128, 1);
    mma_gemm<0, true><<<gOut, blk, GEMM_SMEM>>>(
        Ob, Wob, bo, nullptr, nullptr, out, nullptr, nullptr, EMB, K1, 1.0f, 0, 0, 0);
}

// round 8
// speedup vs baseline: 2.7587x; 1.4796x over previous
#include <cuda_runtime.h>
#include <cuda_fp16.h>
#include <cstdint>

#define SEQ   2048
#define EMB   1024
#define BATCH 4
#define MTOT  (BATCH * SEQ)   // 8192

// 2-segment fp16 split widths
#define K1 (2 * EMB)   // 2048
#define K2 (2 * SEQ)   // 4096

// ---------------- scratch (device globals; allocation-free) ----------------
__device__ __half g_xb  [(long long)MTOT * K1];
__device__ __half g_Wcat[(long long)(3 * EMB) * K1];   // [Wq;Wk;Wv]
__device__ __half g_Wob [(long long)EMB * K1];
__device__ __half g_Qb  [(long long)MTOT * K1];
__device__ __half g_Kb  [(long long)MTOT * K1];
__device__ __half g_VTb [(long long)BATCH * EMB * K2]; // V^T [b][e][2*SEQ]
__device__ float  g_S   [(long long)BATCH * SEQ * SEQ];
__device__ __half g_Pb  [(long long)BATCH * SEQ * K2]; // P [b][q][2*SEQ]
__device__ __half g_Ob  [(long long)MTOT * K1];

// ---------------- helpers ----------------
__device__ __forceinline__ uint32_t smem_to_u32(const void* p) {
    uint32_t a;
    asm("{ .reg .u64 t; cvta.to.shared.u64 t, %1; cvt.u32.u64 %0, t; }" : "=r"(a) : "l"(p));
    return a;
}

#define CP_ASYNC16(dst, src) \
    asm volatile("cp.async.cg.shared.global [%0], [%1], 16;" :: "r"(dst), "l"(src))
#define CP_COMMIT() asm volatile("cp.async.commit_group;" ::: "memory")

__device__ __forceinline__ void ldmatrix_x4(uint32_t& r0, uint32_t& r1, uint32_t& r2, uint32_t& r3,
                                            uint32_t addr) {
    asm volatile("ldmatrix.sync.aligned.m8n8.x4.shared.b16 {%0,%1,%2,%3}, [%4];"
                 : "=r"(r0), "=r"(r1), "=r"(r2), "=r"(r3) : "r"(addr));
}

__device__ __forceinline__ void mma16816(float* c, uint32_t a0, uint32_t a1, uint32_t a2, uint32_t a3,
                                         uint32_t b0, uint32_t b1) {
    asm volatile("mma.sync.aligned.m16n8k16.row.col.f32.f16.f16.f32 "
                 "{%0,%1,%2,%3}, {%4,%5,%6,%7}, {%8,%9}, {%0,%1,%2,%3};"
                 : "+f"(c[0]), "+f"(c[1]), "+f"(c[2]), "+f"(c[3])
                 : "r"(a0), "r"(a1), "r"(a2), "r"(a3), "r"(b0), "r"(b1));
}

// pack 8 floats into uint4 of hi-fp16 and uint4 of lo-fp16 (Dekker split)
__device__ __forceinline__ void split8h(const float* v, uint4& hi, uint4& lo) {
    uint32_t h[4], l[4];
    #pragma unroll
    for (int i = 0; i < 4; i++) {
        float a = v[2 * i], b = v[2 * i + 1];
        __half ha = __float2half_rn(a);
        __half hb = __float2half_rn(b);
        __half la = __float2half_rn(a - __half2float(ha));
        __half lb = __float2half_rn(b - __half2float(hb));
        __half2 hp = __halves2half2(ha, hb);
        __half2 lp = __halves2half2(la, lb);
        h[i] = *(uint32_t*)&hp;
        l[i] = *(uint32_t*)&lp;
    }
    hi = make_uint4(h[0], h[1], h[2], h[3]);
    lo = make_uint4(l[0], l[1], l[2], l[3]);
}

// ---------------- conversions (8 elems/thread, 16B stores) ----------------
// fp32 [rows,1024] -> fp16 split [hi|lo] along K (row stride 2048)
__global__ __launch_bounds__(256)
void cvt_x(const float* __restrict__ in, __half* __restrict__ out)
{
    long long idx = (long long)blockIdx.x * blockDim.x + threadIdx.x;  // 8-elem units
    long long r = idx >> 7;
    int c8 = (int)(idx & 127);
    const float4* src = (const float4*)(in + r * EMB + c8 * 8);
    float v[8];
    float4 f0 = src[0], f1 = src[1];
    v[0]=f0.x; v[1]=f0.y; v[2]=f0.z; v[3]=f0.w;
    v[4]=f1.x; v[5]=f1.y; v[6]=f1.z; v[7]=f1.w;
    uint4 hi, lo;
    split8h(v, hi, lo);
    long long ro = r * (long long)K1 + c8 * 8;
    *(uint4*)(out + ro)       = hi;
    *(uint4*)(out + ro + EMB) = lo;
}

__global__ __launch_bounds__(256)
void cvt_weights(const float* __restrict__ Wq, const float* __restrict__ Wk,
                 const float* __restrict__ Wv, const float* __restrict__ Wo,
                 __half* __restrict__ Wcat, __half* __restrict__ Wob)
{
    int w = blockIdx.y;
    const float* src = (w == 0) ? Wq : (w == 1) ? Wk : (w == 2) ? Wv : Wo;
    long long idx = (long long)blockIdx.x * blockDim.x + threadIdx.x;
    long long r = idx >> 7;
    int c8 = (int)(idx & 127);
    const float4* s4 = (const float4*)(src + r * EMB + c8 * 8);
    float v[8];
    float4 f0 = s4[0], f1 = s4[1];
    v[0]=f0.x; v[1]=f0.y; v[2]=f0.z; v[3]=f0.w;
    v[4]=f1.x; v[5]=f1.y; v[6]=f1.z; v[7]=f1.w;
    uint4 hi, lo;
    split8h(v, hi, lo);
    __half* out = (w < 3) ? (Wcat + (long long)w * EMB * K1) : Wob;
    long long ro = r * (long long)K1 + c8 * 8;
    *(uint4*)(out + ro)       = hi;
    *(uint4*)(out + ro + EMB) = lo;
}

// ---------------- epilogue writers ----------------
__device__ __forceinline__ void write_split(__half* O, int gm, int gn, int Nl,
                                            float v0, float v1) {
    long long ro = (long long)gm * (2LL * Nl);
    __half h0 = __float2half_rn(v0);
    __half l0 = __float2half_rn(v0 - __half2float(h0));
    __half h1 = __float2half_rn(v1);
    __half l1 = __float2half_rn(v1 - __half2float(h1));
    __half2 hp = __halves2half2(h0, h1);
    __half2 lp = __halves2half2(l0, l1);
    *(__half2*)&O[ro + gn]      = hp;
    *(__half2*)&O[ro + Nl + gn] = lp;
}
__device__ __forceinline__ void write_splitT(__half* O, int gm, int gn, int Nl,
                                             float v0, float v1) {
    // V^T: O[b][n][2*SEQ]: [s]=hi, [SEQ+s]=lo
    int b = gm >> 11;
    int sdx = gm & (SEQ - 1);
    #pragma unroll
    for (int e = 0; e < 2; e++) {
        float v = e ? v1 : v0;
        int n = gn + e;
        __half h = __float2half_rn(v);
        __half l = __float2half_rn(v - __half2float(h));
        long long base = (long long)b * Nl * (2LL * SEQ) + (long long)n * (2LL * SEQ) + sdx;
        O[base] = h;
        O[base + SEQ] = l;
    }
}

// ---------------- HMMA GEMM (R6-proven core, fp16 operands) ----------------
// Block 128x128, BK=64, NSTAGE=3, 8 warps (4M x 2N), warp tile 32x64.
// EPI: 0=fp32 out; 1=split out; 4=fused QKV (region 0,1 -> split, 2 -> splitT)
#define BK      64
#define NSTAGE  3
#define STAGE_BYTES 32768
#define GEMM_SMEM (NSTAGE * STAGE_BYTES)

template <int EPI, bool HAS_BIAS>
__global__ __launch_bounds__(256, 2)
void mma_gemm(const __half* __restrict__ A, const __half* __restrict__ B,
              const float* __restrict__ b0, const float* __restrict__ b1,
              const float* __restrict__ b2,
              void* __restrict__ O0, void* __restrict__ O1, void* __restrict__ O2,
              int Nlog, int Ktot, float alpha,
              long long sA, long long sB, long long sO)
{
    extern __shared__ __align__(1024) char smem[];
    const uint32_t smem_base = smem_to_u32(smem);
    const int tid = threadIdx.x;
    const int wid = tid >> 5;
    const int lane = tid & 31;
    const int warp_m = wid & 3;
    const int warp_n = wid >> 2;

    A += (long long)blockIdx.z * sA;
    B += (long long)blockIdx.z * sB;

    const int m0 = blockIdx.y * 128;
    const int n0 = blockIdx.x * 128;

    const int nchunks = Ktot / BK;

    auto load_stage = [&](int chunk, int s) {
        uint32_t sa = smem_base + s * STAGE_BYTES;
        uint32_t sb = sa + 16384;
        long long k0 = (long long)chunk * BK;
        #pragma unroll
        for (int t = 0; t < 4; t++) {
            int idx = tid + t * 256;
            int r = idx >> 3, c = idx & 7;
            uint32_t off = (uint32_t)((r * 8 + (c ^ (r & 7))) * 16);
            CP_ASYNC16(sa + off, (const void*)(A + (long long)(m0 + r) * Ktot + k0 + c * 8));
            CP_ASYNC16(sb + off, (const void*)(B + (long long)(n0 + r) * Ktot + k0 + c * 8));
        }
        CP_COMMIT();
    };

    float acc[2][8][4];
    #pragma unroll
    for (int mi = 0; mi < 2; mi++)
        #pragma unroll
        for (int ni = 0; ni < 8; ni++)
            #pragma unroll
            for (int r = 0; r < 4; r++)
                acc[mi][ni][r] = 0.0f;

    load_stage(0, 0);
    load_stage(1, 1);

    const int a_row = (lane & 15);
    const int a_half = lane >> 4;
    const int b_noff = (lane & 7) + ((lane & 16) ? 8 : 0);
    const int b_kg = (lane & 8) ? 1 : 0;

    for (int i = 0; i < nchunks; i++) {
        if (i + 1 < nchunks) {
            asm volatile("cp.async.wait_group 1;" ::: "memory");
        } else {
            asm volatile("cp.async.wait_group 0;" ::: "memory");
        }
        __syncthreads();

        if (i + 2 < nchunks) load_stage(i + 2, (i + 2) % NSTAGE);

        const int s = i % NSTAGE;
        const uint32_t sa = smem_base + s * STAGE_BYTES;
        const uint32_t sb = sa + 16384;

        #pragma unroll
        for (int kk = 0; kk < 4; kk++) {
            uint32_t af[2][4];
            #pragma unroll
            for (int mi = 0; mi < 2; mi++) {
                int row = warp_m * 32 + mi * 16 + a_row;
                int g = (kk * 2 + a_half) ^ (row & 7);
                ldmatrix_x4(af[mi][0], af[mi][1], af[mi][2], af[mi][3],
                            sa + (uint32_t)((row * 8 + g) * 16));
            }
            uint32_t bf[4][4];
            #pragma unroll
            for (int nt = 0; nt < 4; nt++) {
                int row = warp_n * 64 + nt * 16 + b_noff;
                int g = (kk * 2 + b_kg) ^ (row & 7);
                ldmatrix_x4(bf[nt][0], bf[nt][1], bf[nt][2], bf[nt][3],
                            sb + (uint32_t)((row * 8 + g) * 16));
            }
            #pragma unroll
            for (int mi = 0; mi < 2; mi++)
                #pragma unroll
                for (int ni = 0; ni < 8; ni++) {
                    int nt = ni >> 1;
                    uint32_t bb0 = (ni & 1) ? bf[nt][2] : bf[nt][0];
                    uint32_t bb1 = (ni & 1) ? bf[nt][3] : bf[nt][1];
                    mma16816(acc[mi][ni], af[mi][0], af[mi][1], af[mi][2], af[mi][3], bb0, bb1);
                }
        }
    }

    // ---- epilogue ----
    const int rbase = m0 + warp_m * 32 + (lane >> 2);
    const int cbase = n0 + warp_n * 64 + (lane & 3) * 2;

    int region = 0;
    const float* biasp = b0;
    __half* Oq = (__half*)O0;
    if (EPI == 4) {
        region = n0 >> 10;
        biasp = (region == 0) ? b0 : (region == 1) ? b1 : b2;
        Oq = (region == 0) ? (__half*)O0
           : (region == 1) ? (__half*)O1 : (__half*)O2;
    }

    #pragma unroll
    for (int mi = 0; mi < 2; mi++) {
        #pragma unroll
        for (int ni = 0; ni < 8; ni++) {
            #pragma unroll
            for (int half = 0; half < 2; half++) {
                int gm = rbase + mi * 16 + half * 8;
                int gn = cbase + ni * 8;
                float v0 = acc[mi][ni][half * 2 + 0] * alpha;
                float v1 = acc[mi][ni][half * 2 + 1] * alpha;
                if (EPI == 0) {
                    if (HAS_BIAS) { v0 += b0[gn]; v1 += b0[gn + 1]; }
                    float* O = (float*)O0 + (long long)blockIdx.z * sO;
                    *(float2*)&O[(long long)gm * Nlog + gn] = make_float2(v0, v1);
                } else if (EPI == 1) {
                    if (HAS_BIAS) { v0 += b0[gn]; v1 += b0[gn + 1]; }
                    __half* O = (__half*)O0 + (long long)blockIdx.z * sO;
                    write_split(O, gm, gn, Nlog, v0, v1);
                } else { // EPI == 4 (fused QKV)
                    int nl = gn & (EMB - 1);
                    if (HAS_BIAS) { v0 += biasp[nl]; v1 += biasp[nl + 1]; }
                    if (region < 2) write_split (Oq, gm, nl, EMB, v0, v1);
                    else            write_splitT(Oq, gm, nl, EMB, v0, v1);
                }
            }
        }
    }
}

// ---------------- softmax: fp32 in -> fp16 split P ----------------
__global__ __launch_bounds__(256)
void softmax_split(const float* __restrict__ S, __half* __restrict__ P)
{
    long long row = blockIdx.x;
    const float4* in4 = (const float4*)(S + row * SEQ);
    __half* out = P + row * (2LL * SEQ);
    const int tid = threadIdx.x;
    const int lid = tid & 31;
    const int wid = tid >> 5;

    float v[8];
    {
        float4 f0 = in4[tid * 2];
        float4 f1 = in4[tid * 2 + 1];
        v[0]=f0.x; v[1]=f0.y; v[2]=f0.z; v[3]=f0.w;
        v[4]=f1.x; v[5]=f1.y; v[6]=f1.z; v[7]=f1.w;
    }
    float mx = v[0];
    #pragma unroll
    for (int i = 1; i < 8; i++) mx = fmaxf(mx, v[i]);
    #pragma unroll
    for (int o = 16; o > 0; o >>= 1)
        mx = fmaxf(mx, __shfl_xor_sync(0xffffffffu, mx, o));

    __shared__ float smax[8], ssum[8];
    if (lid == 0) smax[wid] = mx;
    __syncthreads();
    mx = smax[0];
    #pragma unroll
    for (int w = 1; w < 8; w++) mx = fmaxf(mx, smax[w]);

    float sum = 0.0f;
    #pragma unroll
    for (int i = 0; i < 8; i++) {
        v[i] = __expf(v[i] - mx);
        sum += v[i];
    }
    #pragma unroll
    for (int o = 16; o > 0; o >>= 1)
        sum += __shfl_xor_sync(0xffffffffu, sum, o);
    if (lid == 0) ssum[wid] = sum;
    __syncthreads();
    sum = 0.0f;
    #pragma unroll
    for (int w = 0; w < 8; w++) sum += ssum[w];

    float inv = 1.0f / sum;
    #pragma unroll
    for (int i = 0; i < 8; i++) v[i] *= inv;

    uint4 hi, lo;
    split8h(v, hi, lo);
    int col = tid * 8;
    *(uint4*)(out + col)       = hi;
    *(uint4*)(out + SEQ + col) = lo;
}

// ---------------- launch ----------------
extern "C" void kernel_launch(void* const* d_in, const int* in_sizes, int n_in,
                              void* d_out, int out_size)
{
    const float* x  = (const float*)d_in[0];
    const float* Wq = (const float*)d_in[1];
    const float* bq = (const float*)d_in[2];
    const float* Wk = (const float*)d_in[3];
    const float* bk = (const float*)d_in[4];
    const float* Wv = (const float*)d_in[5];
    const float* bv = (const float*)d_in[6];
    const float* Wo = (const float*)d_in[7];
    const float* bo = (const float*)d_in[8];
    float* out = (float*)d_out;

    __half *xb, *Wcat, *Wob, *Qb, *Kb, *VTb, *Pb, *Ob;
    float* S;
    cudaGetSymbolAddress((void**)&xb,   g_xb);
    cudaGetSymbolAddress((void**)&Wcat, g_Wcat);
    cudaGetSymbolAddress((void**)&Wob,  g_Wob);
    cudaGetSymbolAddress((void**)&Qb,   g_Qb);
    cudaGetSymbolAddress((void**)&Kb,   g_Kb);
    cudaGetSymbolAddress((void**)&VTb,  g_VTb);
    cudaGetSymbolAddress((void**)&S,    g_S);
    cudaGetSymbolAddress((void**)&Pb,   g_Pb);
    cudaGetSymbolAddress((void**)&Ob,   g_Ob);

    cudaFuncSetAttribute(mma_gemm<0, false>, cudaFuncAttributeMaxDynamicSharedMemorySize, GEMM_SMEM);
    cudaFuncSetAttribute(mma_gemm<0, true >, cudaFuncAttributeMaxDynamicSharedMemorySize, GEMM_SMEM);
    cudaFuncSetAttribute(mma_gemm<1, false>, cudaFuncAttributeMaxDynamicSharedMemorySize, GEMM_SMEM);
    cudaFuncSetAttribute(mma_gemm<4, true >, cudaFuncAttributeMaxDynamicSharedMemorySize, GEMM_SMEM);

    dim3 blk(256);
    const float scale = 1.0f / 32.0f;

    // 1) conversions
    cvt_x<<<(unsigned)(((long long)MTOT * EMB / 8) / 256), 256>>>(x, xb);
    {
        dim3 gw((unsigned)(((long long)EMB * EMB / 8) / 256), 4);
        cvt_weights<<<gw, 256>>>(Wq, Wk, Wv, Wo, Wcat, Wob);
    }

    // 2) fused QKV projection: [8192,2048] x [3072,2048]^T
    dim3 gQKV(3 * EMB / 128, MTOT / 128, 1);
    mma_gemm<4, true><<<gQKV, blk, GEMM_SMEM>>>(
        xb, Wcat, bq, bk, bv, Qb, Kb, VTb, EMB, K1, 1.0f, 0, 0, 0);

    // 3) scores = scale * Q K^T (fp32)
    dim3 gScore(SEQ / 128, SEQ / 128, BATCH);
    mma_gemm<0, false><<<gScore, blk, GEMM_SMEM>>>(
        Qb, Kb, nullptr, nullptr, nullptr, S, nullptr, nullptr, SEQ, K1, scale,
        (long long)SEQ * K1, (long long)SEQ * K1, (long long)SEQ * SEQ);

    // 4) softmax -> split P
    softmax_split<<<BATCH * SEQ, blk>>>(S, Pb);

    // 5) O = P V : A=Pb [2048,4096], B=VTb [1024,4096] per batch
    dim3 gPV(EMB / 128, SEQ / 128, BATCH);
    mma_gemm<1, false><<<gPV, blk, GEMM_SMEM>>>(
        Pb, VTb, nullptr, nullptr, nullptr, Ob, nullptr, nullptr, EMB, K2, 1.0f,
        (long long)SEQ * K2, (long long)EMB * K2, (long long)SEQ * K1);

    // 6) out = O Wo^T + bo (fp32)
    dim3 gOut(EMB / 128, MTOT / 128, 1);
    mma_gemm<0, true><<<gOut, blk, GEMM_SMEM>>>(
        Ob, Wob, bo, nullptr, nullptr, out, nullptr, nullptr, EMB, K1, 1.0f, 0, 0, 0);
}

// round 9
// speedup vs baseline: 2.7634x; 1.0017x over previous
#include <cuda_runtime.h>
#include <cuda_fp16.h>
#include <cstdint>

#define SEQ   2048
#define EMB   1024
#define BATCH 4
#define MTOT  (BATCH * SEQ)   // 8192

// 2-segment fp16 split widths
#define K1 (2 * EMB)   // 2048
#define K2 (2 * SEQ)   // 4096

// ---------------- scratch (device globals; allocation-free) ----------------
__device__ __half g_xb  [(long long)MTOT * K1];
__device__ __half g_Wcat[(long long)(3 * EMB) * K1];   // [Wq;Wk;Wv]
__device__ __half g_Wob [(long long)EMB * K1];
__device__ __half g_Qb  [(long long)MTOT * K1];
__device__ __half g_Kb  [(long long)MTOT * K1];
__device__ __half g_VTb [(long long)BATCH * EMB * K2]; // V^T [b][e][2*SEQ]
__device__ float  g_S   [(long long)BATCH * SEQ * SEQ];
__device__ __half g_Pb  [(long long)BATCH * SEQ * K2]; // P [b][q][2*SEQ]
__device__ __half g_Ob  [(long long)MTOT * K1];

// ---------------- helpers ----------------
__device__ __forceinline__ uint32_t smem_to_u32(const void* p) {
    uint32_t a;
    asm("{ .reg .u64 t; cvta.to.shared.u64 t, %1; cvt.u32.u64 %0, t; }" : "=r"(a) : "l"(p));
    return a;
}

#define CP_ASYNC16(dst, src) \
    asm volatile("cp.async.cg.shared.global [%0], [%1], 16;" :: "r"(dst), "l"(src))
#define CP_COMMIT() asm volatile("cp.async.commit_group;" ::: "memory")

__device__ __forceinline__ void ldmatrix_x4(uint32_t& r0, uint32_t& r1, uint32_t& r2, uint32_t& r3,
                                            uint32_t addr) {
    asm volatile("ldmatrix.sync.aligned.m8n8.x4.shared.b16 {%0,%1,%2,%3}, [%4];"
                 : "=r"(r0), "=r"(r1), "=r"(r2), "=r"(r3) : "r"(addr));
}

__device__ __forceinline__ void mma16816(float* c, uint32_t a0, uint32_t a1, uint32_t a2, uint32_t a3,
                                         uint32_t b0, uint32_t b1) {
    asm volatile("mma.sync.aligned.m16n8k16.row.col.f32.f16.f16.f32 "
                 "{%0,%1,%2,%3}, {%4,%5,%6,%7}, {%8,%9}, {%0,%1,%2,%3};"
                 : "+f"(c[0]), "+f"(c[1]), "+f"(c[2]), "+f"(c[3])
                 : "r"(a0), "r"(a1), "r"(a2), "r"(a3), "r"(b0), "r"(b1));
}

// pack 8 floats into uint4 of hi-fp16 and uint4 of lo-fp16 (Dekker split)
__device__ __forceinline__ void split8h(const float* v, uint4& hi, uint4& lo) {
    uint32_t h[4], l[4];
    #pragma unroll
    for (int i = 0; i < 4; i++) {
        float a = v[2 * i], b = v[2 * i + 1];
        __half ha = __float2half_rn(a);
        __half hb = __float2half_rn(b);
        __half la = __float2half_rn(a - __half2float(ha));
        __half lb = __float2half_rn(b - __half2float(hb));
        __half2 hp = __halves2half2(ha, hb);
        __half2 lp = __halves2half2(la, lb);
        h[i] = *(uint32_t*)&hp;
        l[i] = *(uint32_t*)&lp;
    }
    hi = make_uint4(h[0], h[1], h[2], h[3]);
    lo = make_uint4(l[0], l[1], l[2], l[3]);
}

// ---------------- conversions (8 elems/thread, 16B stores) ----------------
// fp32 [rows,1024] -> fp16 split [hi|lo] along K (row stride 2048)
__global__ __launch_bounds__(256)
void cvt_x(const float* __restrict__ in, __half* __restrict__ out)
{
    long long idx = (long long)blockIdx.x * blockDim.x + threadIdx.x;  // 8-elem units
    long long r = idx >> 7;
    int c8 = (int)(idx & 127);
    const float4* src = (const float4*)(in + r * EMB + c8 * 8);
    float v[8];
    float4 f0 = src[0], f1 = src[1];
    v[0]=f0.x; v[1]=f0.y; v[2]=f0.z; v[3]=f0.w;
    v[4]=f1.x; v[5]=f1.y; v[6]=f1.z; v[7]=f1.w;
    uint4 hi, lo;
    split8h(v, hi, lo);
    long long ro = r * (long long)K1 + c8 * 8;
    *(uint4*)(out + ro)       = hi;
    *(uint4*)(out + ro + EMB) = lo;
}

__global__ __launch_bounds__(256)
void cvt_weights(const float* __restrict__ Wq, const float* __restrict__ Wk,
                 const float* __restrict__ Wv, const float* __restrict__ Wo,
                 __half* __restrict__ Wcat, __half* __restrict__ Wob)
{
    int w = blockIdx.y;
    const float* src = (w == 0) ? Wq : (w == 1) ? Wk : (w == 2) ? Wv : Wo;
    long long idx = (long long)blockIdx.x * blockDim.x + threadIdx.x;
    long long r = idx >> 7;
    int c8 = (int)(idx & 127);
    const float4* s4 = (const float4*)(src + r * EMB + c8 * 8);
    float v[8];
    float4 f0 = s4[0], f1 = s4[1];
    v[0]=f0.x; v[1]=f0.y; v[2]=f0.z; v[3]=f0.w;
    v[4]=f1.x; v[5]=f1.y; v[6]=f1.z; v[7]=f1.w;
    uint4 hi, lo;
    split8h(v, hi, lo);
    __half* out = (w < 3) ? (Wcat + (long long)w * EMB * K1) : Wob;
    long long ro = r * (long long)K1 + c8 * 8;
    *(uint4*)(out + ro)       = hi;
    *(uint4*)(out + ro + EMB) = lo;
}

// ---------------- epilogue writers ----------------
__device__ __forceinline__ void write_split(__half* O, int gm, int gn, int Nl,
                                            float v0, float v1) {
    long long ro = (long long)gm * (2LL * Nl);
    __half h0 = __float2half_rn(v0);
    __half l0 = __float2half_rn(v0 - __half2float(h0));
    __half h1 = __float2half_rn(v1);
    __half l1 = __float2half_rn(v1 - __half2float(h1));
    __half2 hp = __halves2half2(h0, h1);
    __half2 lp = __halves2half2(l0, l1);
    *(__half2*)&O[ro + gn]      = hp;
    *(__half2*)&O[ro + Nl + gn] = lp;
}
__device__ __forceinline__ void write_splitT(__half* O, int gm, int gn, int Nl,
                                             float v0, float v1) {
    // V^T: O[b][n][2*SEQ]: [s]=hi, [SEQ+s]=lo
    int b = gm >> 11;
    int sdx = gm & (SEQ - 1);
    #pragma unroll
    for (int e = 0; e < 2; e++) {
        float v = e ? v1 : v0;
        int n = gn + e;
        __half h = __float2half_rn(v);
        __half l = __float2half_rn(v - __half2float(h));
        long long base = (long long)b * Nl * (2LL * SEQ) + (long long)n * (2LL * SEQ) + sdx;
        O[base] = h;
        O[base + SEQ] = l;
    }
}

// ---------------- HMMA GEMM (R6-proven core, fp16 operands) ----------------
// Block 128x128, BK=64, NSTAGE=3, 8 warps (4M x 2N), warp tile 32x64.
// EPI: 0=fp32 out; 1=split out; 4=fused QKV (region 0,1 -> split, 2 -> splitT)
#define BK      64
#define NSTAGE  3
#define STAGE_BYTES 32768
#define GEMM_SMEM (NSTAGE * STAGE_BYTES)

template <int EPI, bool HAS_BIAS>
__global__ __launch_bounds__(256, 2)
void mma_gemm(const __half* __restrict__ A, const __half* __restrict__ B,
              const float* __restrict__ b0, const float* __restrict__ b1,
              const float* __restrict__ b2,
              void* __restrict__ O0, void* __restrict__ O1, void* __restrict__ O2,
              int Nlog, int Ktot, float alpha,
              long long sA, long long sB, long long sO)
{
    extern __shared__ __align__(1024) char smem[];
    const uint32_t smem_base = smem_to_u32(smem);
    const int tid = threadIdx.x;
    const int wid = tid >> 5;
    const int lane = tid & 31;
    const int warp_m = wid & 3;
    const int warp_n = wid >> 2;

    A += (long long)blockIdx.z * sA;
    B += (long long)blockIdx.z * sB;

    const int m0 = blockIdx.y * 128;
    const int n0 = blockIdx.x * 128;

    const int nchunks = Ktot / BK;

    auto load_stage = [&](int chunk, int s) {
        uint32_t sa = smem_base + s * STAGE_BYTES;
        uint32_t sb = sa + 16384;
        long long k0 = (long long)chunk * BK;
        #pragma unroll
        for (int t = 0; t < 4; t++) {
            int idx = tid + t * 256;
            int r = idx >> 3, c = idx & 7;
            uint32_t off = (uint32_t)((r * 8 + (c ^ (r & 7))) * 16);
            CP_ASYNC16(sa + off, (const void*)(A + (long long)(m0 + r) * Ktot + k0 + c * 8));
            CP_ASYNC16(sb + off, (const void*)(B + (long long)(n0 + r) * Ktot + k0 + c * 8));
        }
        CP_COMMIT();
    };

    float acc[2][8][4];
    #pragma unroll
    for (int mi = 0; mi < 2; mi++)
        #pragma unroll
        for (int ni = 0; ni < 8; ni++)
            #pragma unroll
            for (int r = 0; r < 4; r++)
                acc[mi][ni][r] = 0.0f;

    load_stage(0, 0);
    load_stage(1, 1);

    const int a_row = (lane & 15);
    const int a_half = lane >> 4;
    const int b_noff = (lane & 7) + ((lane & 16) ? 8 : 0);
    const int b_kg = (lane & 8) ? 1 : 0;

    for (int i = 0; i < nchunks; i++) {
        if (i + 1 < nchunks) {
            asm volatile("cp.async.wait_group 1;" ::: "memory");
        } else {
            asm volatile("cp.async.wait_group 0;" ::: "memory");
        }
        __syncthreads();

        if (i + 2 < nchunks) load_stage(i + 2, (i + 2) % NSTAGE);

        const int s = i % NSTAGE;
        const uint32_t sa = smem_base + s * STAGE_BYTES;
        const uint32_t sb = sa + 16384;

        #pragma unroll
        for (int kk = 0; kk < 4; kk++) {
            uint32_t af[2][4];
            #pragma unroll
            for (int mi = 0; mi < 2; mi++) {
                int row = warp_m * 32 + mi * 16 + a_row;
                int g = (kk * 2 + a_half) ^ (row & 7);
                ldmatrix_x4(af[mi][0], af[mi][1], af[mi][2], af[mi][3],
                            sa + (uint32_t)((row * 8 + g) * 16));
            }
            uint32_t bf[4][4];
            #pragma unroll
            for (int nt = 0; nt < 4; nt++) {
                int row = warp_n * 64 + nt * 16 + b_noff;
                int g = (kk * 2 + b_kg) ^ (row & 7);
                ldmatrix_x4(bf[nt][0], bf[nt][1], bf[nt][2], bf[nt][3],
                            sb + (uint32_t)((row * 8 + g) * 16));
            }
            #pragma unroll
            for (int mi = 0; mi < 2; mi++)
                #pragma unroll
                for (int ni = 0; ni < 8; ni++) {
                    int nt = ni >> 1;
                    uint32_t bb0 = (ni & 1) ? bf[nt][2] : bf[nt][0];
                    uint32_t bb1 = (ni & 1) ? bf[nt][3] : bf[nt][1];
                    mma16816(acc[mi][ni], af[mi][0], af[mi][1], af[mi][2], af[mi][3], bb0, bb1);
                }
        }
    }

    // ---- epilogue ----
    const int rbase = m0 + warp_m * 32 + (lane >> 2);
    const int cbase = n0 + warp_n * 64 + (lane & 3) * 2;

    int region = 0;
    const float* biasp = b0;
    __half* Oq = (__half*)O0;
    if (EPI == 4) {
        region = n0 >> 10;
        biasp = (region == 0) ? b0 : (region == 1) ? b1 : b2;
        Oq = (region == 0) ? (__half*)O0
           : (region == 1) ? (__half*)O1 : (__half*)O2;
    }

    #pragma unroll
    for (int mi = 0; mi < 2; mi++) {
        #pragma unroll
        for (int ni = 0; ni < 8; ni++) {
            #pragma unroll
            for (int half = 0; half < 2; half++) {
                int gm = rbase + mi * 16 + half * 8;
                int gn = cbase + ni * 8;
                float v0 = acc[mi][ni][half * 2 + 0] * alpha;
                float v1 = acc[mi][ni][half * 2 + 1] * alpha;
                if (EPI == 0) {
                    if (HAS_BIAS) { v0 += b0[gn]; v1 += b0[gn + 1]; }
                    float* O = (float*)O0 + (long long)blockIdx.z * sO;
                    *(float2*)&O[(long long)gm * Nlog + gn] = make_float2(v0, v1);
                } else if (EPI == 1) {
                    if (HAS_BIAS) { v0 += b0[gn]; v1 += b0[gn + 1]; }
                    __half* O = (__half*)O0 + (long long)blockIdx.z * sO;
                    write_split(O, gm, gn, Nlog, v0, v1);
                } else { // EPI == 4 (fused QKV)
                    int nl = gn & (EMB - 1);
                    if (HAS_BIAS) { v0 += biasp[nl]; v1 += biasp[nl + 1]; }
                    if (region < 2) write_split (Oq, gm, nl, EMB, v0, v1);
                    else            write_splitT(Oq, gm, nl, EMB, v0, v1);
                }
            }
        }
    }
}

// ---------------- softmax: fp32 in -> fp16 split P ----------------
__global__ __launch_bounds__(256)
void softmax_split(const float* __restrict__ S, __half* __restrict__ P)
{
    long long row = blockIdx.x;
    const float4* in4 = (const float4*)(S + row * SEQ);
    __half* out = P + row * (2LL * SEQ);
    const int tid = threadIdx.x;
    const int lid = tid & 31;
    const int wid = tid >> 5;

    float v[8];
    {
        float4 f0 = in4[tid * 2];
        float4 f1 = in4[tid * 2 + 1];
        v[0]=f0.x; v[1]=f0.y; v[2]=f0.z; v[3]=f0.w;
        v[4]=f1.x; v[5]=f1.y; v[6]=f1.z; v[7]=f1.w;
    }
    float mx = v[0];
    #pragma unroll
    for (int i = 1; i < 8; i++) mx = fmaxf(mx, v[i]);
    #pragma unroll
    for (int o = 16; o > 0; o >>= 1)
        mx = fmaxf(mx, __shfl_xor_sync(0xffffffffu, mx, o));

    __shared__ float smax[8], ssum[8];
    if (lid == 0) smax[wid] = mx;
    __syncthreads();
    mx = smax[0];
    #pragma unroll
    for (int w = 1; w < 8; w++) mx = fmaxf(mx, smax[w]);

    float sum = 0.0f;
    #pragma unroll
    for (int i = 0; i < 8; i++) {
        v[i] = __expf(v[i] - mx);
        sum += v[i];
    }
    #pragma unroll
    for (int o = 16; o > 0; o >>= 1)
        sum += __shfl_xor_sync(0xffffffffu, sum, o);
    if (lid == 0) ssum[wid] = sum;
    __syncthreads();
    sum = 0.0f;
    #pragma unroll
    for (int w = 0; w < 8; w++) sum += ssum[w];

    float inv = 1.0f / sum;
    #pragma unroll
    for (int i = 0; i < 8; i++) v[i] *= inv;

    uint4 hi, lo;
    split8h(v, hi, lo);
    int col = tid * 8;
    *(uint4*)(out + col)       = hi;
    *(uint4*)(out + SEQ + col) = lo;
}

// ---------------- launch ----------------
extern "C" void kernel_launch(void* const* d_in, const int* in_sizes, int n_in,
                              void* d_out, int out_size)
{
    const float* x  = (const float*)d_in[0];
    const float* Wq = (const float*)d_in[1];
    const float* bq = (const float*)d_in[2];
    const float* Wk = (const float*)d_in[3];
    const float* bk = (const float*)d_in[4];
    const float* Wv = (const float*)d_in[5];
    const float* bv = (const float*)d_in[6];
    const float* Wo = (const float*)d_in[7];
    const float* bo = (const float*)d_in[8];
    float* out = (float*)d_out;

    __half *xb, *Wcat, *Wob, *Qb, *Kb, *VTb, *Pb, *Ob;
    float* S;
    cudaGetSymbolAddress((void**)&xb,   g_xb);
    cudaGetSymbolAddress((void**)&Wcat, g_Wcat);
    cudaGetSymbolAddress((void**)&Wob,  g_Wob);
    cudaGetSymbolAddress((void**)&Qb,   g_Qb);
    cudaGetSymbolAddress((void**)&Kb,   g_Kb);
    cudaGetSymbolAddress((void**)&VTb,  g_VTb);
    cudaGetSymbolAddress((void**)&S,    g_S);
    cudaGetSymbolAddress((void**)&Pb,   g_Pb);
    cudaGetSymbolAddress((void**)&Ob,   g_Ob);

    cudaFuncSetAttribute(mma_gemm<0, false>, cudaFuncAttributeMaxDynamicSharedMemorySize, GEMM_SMEM);
    cudaFuncSetAttribute(mma_gemm<0, true >, cudaFuncAttributeMaxDynamicSharedMemorySize, GEMM_SMEM);
    cudaFuncSetAttribute(mma_gemm<1, false>, cudaFuncAttributeMaxDynamicSharedMemorySize, GEMM_SMEM);
    cudaFuncSetAttribute(mma_gemm<4, true >, cudaFuncAttributeMaxDynamicSharedMemorySize, GEMM_SMEM);

    dim3 blk(256);
    const float scale = 1.0f / 32.0f;

    // 1) conversions
    cvt_x<<<(unsigned)(((long long)MTOT * EMB / 8) / 256), 256>>>(x, xb);
    {
        dim3 gw((unsigned)(((long long)EMB * EMB / 8) / 256), 4);
        cvt_weights<<<gw, 256>>>(Wq, Wk, Wv, Wo, Wcat, Wob);
    }

    // 2) fused QKV projection: [8192,2048] x [3072,2048]^T
    dim3 gQKV(3 * EMB / 128, MTOT / 128, 1);
    mma_gemm<4, true><<<gQKV, blk, GEMM_SMEM>>>(
        xb, Wcat, bq, bk, bv, Qb, Kb, VTb, EMB, K1, 1.0f, 0, 0, 0);

    // 3) scores = scale * Q K^T (fp32)
    dim3 gScore(SEQ / 128, SEQ / 128, BATCH);
    mma_gemm<0, false><<<gScore, blk, GEMM_SMEM>>>(
        Qb, Kb, nullptr, nullptr, nullptr, S, nullptr, nullptr, SEQ, K1, scale,
        (long long)SEQ * K1, (long long)SEQ * K1, (long long)SEQ * SEQ);

    // 4) softmax -> split P
    softmax_split<<<BATCH * SEQ, blk>>>(S, Pb);

    // 5) O = P V : A=Pb [2048,4096], B=VTb [1024,4096] per batch
    dim3 gPV(EMB / 128, SEQ / 128, BATCH);
    mma_gemm<1, false><<<gPV, blk, GEMM_SMEM>>>(
        Pb, VTb, nullptr, nullptr, nullptr, Ob, nullptr, nullptr, EMB, K2, 1.0f,
        (long long)SEQ * K2, (long long)EMB * K2, (long long)SEQ * K1);

    // 6) out = O Wo^T + bo (fp32)
    dim3 gOut(EMB / 128, MTOT / 128, 1);
    mma_gemm<0, true><<<gOut, blk, GEMM_SMEM>>>(
        Ob, Wob, bo, nullptr, nullptr, out, nullptr, nullptr, EMB, K1, 1.0f, 0, 0, 0);
}